// round 14
// baseline (speedup 1.0000x reference)
#include <cuda_runtime.h>
#include <cuda_fp16.h>
#include <cstdint>

// ---------------- tiles ----------------
#define BM 128
#define BN1 128
#define BN2 64
#define BK 64
#define STAGES 3
#define ROWB 144
#define A_STAGE_B (BM * ROWB)                     // 18432
#define STAGE_B_MAX (A_STAGE_B + BN1 * ROWB)      // 36864
#define SMEM_BYTES (STAGES * STAGE_B_MAX)         // 110592 (2 CTAs/SM)

// ---------------- ticket layout: V, x, G1, Us, G2A(BN=128), G2B(BN=64 tail) ----------------
#define N_V     32
#define XPB     8
#define T_X0    (N_V)                       // 32
#define T_G1    (T_X0 + 512)                // 544
#define N_G1    512                          // 64 bands x 8 tiles
#define T_US0   (T_G1 + N_G1)               // 1056
#define N_US    32
#define T_G2A   (T_US0 + N_US)              // 1088
#define N_G2A   (56 * 32)                    // bands 0..55, BN=128
#define T_G2B   (T_G2A + N_G2A)             // 2880
#define N_G2B   (8 * 64)                     // bands 56..63, BN=64
#define T_END   (T_G2B + N_G2B)             // 3392

// ---------------- sync counters ----------------
#define C_TICKET 0
#define C_US     1
#define C_V      2
#define C_X      3           // 3..66
#define C_T      67          // 67..130
#define C_NUM    131

__device__ unsigned g_sync[C_NUM];

// ---------------- scratch (allocation-free rule) ----------------
__device__ __align__(1024) __half g_xt[33554432]; // x  -> fp16   [8192,4096]
__device__ __align__(1024) __half g_t [8388608];  // t = x @ V^T  [8192,1024]
__device__ __align__(1024) __half g_Us[4194304];  // (U cat)*s    [4096,1024]
__device__ __align__(1024) __half g_V [4194304];  // V cat        [1024,4096]

// ---------------- helpers ----------------
__device__ __forceinline__ void cp16(uint32_t s, const void* g) {
    asm volatile("cp.async.cg.shared.global [%0], [%1], 16;" :: "r"(s), "l"(g));
}
__device__ __forceinline__ void ldsm4(uint32_t* r, uint32_t addr) {
    asm volatile("ldmatrix.sync.aligned.m8n8.x4.shared.b16 {%0,%1,%2,%3}, [%4];"
                 : "=r"(r[0]), "=r"(r[1]), "=r"(r[2]), "=r"(r[3]) : "r"(addr));
}
__device__ __forceinline__ void mma16(float* c, const uint32_t* a, const uint32_t* b) {
    asm volatile("mma.sync.aligned.m16n8k16.row.col.f32.f16.f16.f32 "
                 "{%0,%1,%2,%3}, {%4,%5,%6,%7}, {%8,%9}, {%0,%1,%2,%3};"
                 : "+f"(c[0]), "+f"(c[1]), "+f"(c[2]), "+f"(c[3])
                 : "r"(a[0]), "r"(a[1]), "r"(a[2]), "r"(a[3]),
                   "r"(b[0]), "r"(b[1]));
}
__device__ __forceinline__ unsigned ldacq(const unsigned* p) {
    unsigned v;
    asm volatile("ld.acquire.gpu.global.u32 %0, [%1];" : "=r"(v) : "l"(p));
    return v;
}
__device__ __forceinline__ void redrel(unsigned* p) {
    asm volatile("red.release.gpu.global.add.u32 [%0], %1;" :: "l"(p), "r"(1u));
}
__device__ __forceinline__ void wait_ge(const unsigned* p, unsigned tgt) {
    while (ldacq(p) < tgt) __nanosleep(64);
}

// ---------------- pack pieces (128 threads each) ----------------
__device__ void pack_us_chunk(int c, const float* u_t, const float* u_d, const float* s) {
    const int base = c * 32768;
    for (int i = threadIdx.x; i < 32768; i += 128) {
        const int idx = base + i;
        const int o = idx >> 8, r4 = idx & 255;
        float4 u = (r4 < 16) ? *(const float4*)(u_t + o * 64 + r4 * 4)
                             : *(const float4*)(u_d + o * 960 + r4 * 4 - 64);
        float4 sv = *(const float4*)(s + r4 * 4);
        __half2 h0 = __float22half2_rn(make_float2(u.x * sv.x, u.y * sv.y));
        __half2 h1 = __float22half2_rn(make_float2(u.z * sv.z, u.w * sv.w));
        *(uint2*)(g_Us + (size_t)idx * 4) = make_uint2(*(uint32_t*)&h0, *(uint32_t*)&h1);
    }
}
__device__ void pack_v_chunk(int c, const float* v_t, const float* v_d) {
    const int base = c * 32768;
    for (int i = threadIdx.x; i < 32768; i += 128) {
        const int idx = base + i;
        const int r = idx >> 10;
        float4 v = (r < 64) ? *(const float4*)(v_t + (size_t)idx * 4)
                            : *(const float4*)(v_d + (size_t)idx * 4 - 64 * 4096);
        __half2 h0 = __float22half2_rn(make_float2(v.x, v.y));
        __half2 h1 = __float22half2_rn(make_float2(v.z, v.w));
        *(uint2*)(g_V + (size_t)idx * 4) = make_uint2(*(uint32_t*)&h0, *(uint32_t*)&h1);
    }
}
__device__ void pack_x_chunk(int q, const float* x) {   // q in 0..511
    const size_t base = (size_t)q * 16384;
    for (int i = threadIdx.x; i < 16384; i += 128) {
        const size_t idx = base + i;
        float4 v = *(const float4*)(x + idx * 4);
        __half2 h0 = __float22half2_rn(make_float2(v.x, v.y));
        __half2 h1 = __float22half2_rn(make_float2(v.z, v.w));
        *(uint2*)(g_xt + idx * 4) = make_uint2(*(uint32_t*)&h0, *(uint32_t*)&h1);
    }
}

// ---------------- GEMM tile: C[BMxBN_T] = A @ B^T (+bias) ----------------
template<bool HALF_OUT, int BN_T>
__device__ void gemm_tile(char* sm, const __half* __restrict__ A, const __half* __restrict__ Bm,
                          const float* __restrict__ bias, void* __restrict__ Cout,
                          int N, int K, int mBase, int nBase)
{
    constexpr int B_STG = BN_T * ROWB;
    constexpr int STG   = A_STAGE_B + B_STG;
    constexpr int NP    = BN_T / 32;

    const uint32_t sbase = (uint32_t)__cvta_generic_to_shared(sm);
    const int tid  = threadIdx.x;
    const int lane = tid & 31;
    const int wid  = tid >> 5;
    const int wm   = wid >> 1;
    const int wn   = wid & 1;
    const int g    = lane >> 2;
    const int tg   = lane & 3;

    const __half* Ag = A  + (size_t)mBase * K;
    const __half* Bg = Bm + (size_t)nBase * K;

    const int aRow = wm * 64 + (lane & 7) + ((lane >> 3) & 1) * 8;
    const int aKb  = (lane >> 4) * 16;
    const uint32_t aOff = (uint32_t)(aRow * ROWB + aKb);
    const int bRow = wn * (BN_T / 2) + (lane & 7) + (lane >> 4) * 8;
    const int bKb  = ((lane >> 3) & 1) * 16;
    const uint32_t bOff = (uint32_t)(bRow * ROWB + bKb) + A_STAGE_B;

    float c[4][2 * NP][4];
#pragma unroll
    for (int mt = 0; mt < 4; mt++)
#pragma unroll
        for (int nt = 0; nt < 2 * NP; nt++)
#pragma unroll
            for (int i = 0; i < 4; i++) c[mt][nt][i] = 0.f;

    auto load_stage = [&](int st, int kt) {
        const uint32_t base = sbase + (uint32_t)st * STG;
        const size_t kOff = (size_t)kt * BK;
#pragma unroll
        for (int i = 0; i < 8; i++) {
            const int cid = i * 128 + tid;
            const int row = cid >> 3;
            const uint32_t colB = (uint32_t)(cid & 7) * 16u;
            cp16(base + (uint32_t)(row * ROWB) + colB,
                 (const char*)(Ag + (size_t)row * K + kOff) + colB);
        }
#pragma unroll
        for (int i = 0; i < BN_T / 16; i++) {
            const int cid = i * 128 + tid;
            const int row = cid >> 3;
            const uint32_t colB = (uint32_t)(cid & 7) * 16u;
            cp16(base + A_STAGE_B + (uint32_t)(row * ROWB) + colB,
                 (const char*)(Bg + (size_t)row * K + kOff) + colB);
        }
        asm volatile("cp.async.commit_group;" ::: "memory");
    };

#pragma unroll
    for (int s = 0; s < STAGES - 1; s++) load_stage(s, s);

    const int KT = K / BK;
    for (int kt = 0; kt < KT; kt++) {
        asm volatile("cp.async.wait_group %0;" :: "n"(STAGES - 2) : "memory");
        __syncthreads();

        const int pf = kt + STAGES - 1;
        if (pf < KT) load_stage(pf % STAGES, pf);
        else asm volatile("cp.async.commit_group;" ::: "memory");

        const uint32_t stBase = sbase + (uint32_t)(kt % STAGES) * STG;

#pragma unroll
        for (int kk = 0; kk < BK / 16; kk++) {
            const uint32_t kByte = (uint32_t)(kk * 32);
            uint32_t a[4][4];
#pragma unroll
            for (int mt = 0; mt < 4; mt++)
                ldsm4(a[mt], stBase + aOff + (uint32_t)(mt * 16 * ROWB) + kByte);
#pragma unroll
            for (int np = 0; np < NP; np++) {
                uint32_t b[4];
                ldsm4(b, stBase + bOff + (uint32_t)(np * 16 * ROWB) + kByte);
#pragma unroll
                for (int mt = 0; mt < 4; mt++) {
                    mma16(c[mt][np * 2],     a[mt], b);
                    mma16(c[mt][np * 2 + 1], a[mt], b + 2);
                }
            }
        }
    }
    __syncthreads();   // stages consumed; smem reusable by next ticket

#pragma unroll
    for (int mt = 0; mt < 4; mt++) {
        const int row = mBase + wm * 64 + mt * 16 + g;
#pragma unroll
        for (int nt = 0; nt < 2 * NP; nt++) {
            const int col = nBase + wn * (BN_T / 2) + nt * 8 + 2 * tg;
            if (HALF_OUT) {
                __half* C = (__half*)Cout;
                *(__half2*)(C + (size_t)row * N + col) =
                    __float22half2_rn(make_float2(c[mt][nt][0], c[mt][nt][1]));
                *(__half2*)(C + (size_t)(row + 8) * N + col) =
                    __float22half2_rn(make_float2(c[mt][nt][2], c[mt][nt][3]));
            } else {
                float* C = (float*)Cout;
                const float b0 = bias[col], b1 = bias[col + 1];
                *(float2*)(C + (size_t)row * N + col) =
                    make_float2(c[mt][nt][0] + b0, c[mt][nt][1] + b1);
                *(float2*)(C + (size_t)(row + 8) * N + col) =
                    make_float2(c[mt][nt][2] + b0, c[mt][nt][3] + b1);
            }
        }
    }
}

// ---------------- fused persistent kernel ----------------
__global__ void __launch_bounds__(128, 2)
siva_fused(const float* __restrict__ x,
           const float* __restrict__ u_t, const float* __restrict__ u_d,
           const float* __restrict__ s,
           const float* __restrict__ v_t, const float* __restrict__ v_d,
           const float* __restrict__ bias, float* __restrict__ out)
{
    extern __shared__ __align__(16) char sm[];
    __shared__ unsigned s_tk;
    const int tid = threadIdx.x;

    for (;;) {
        if (tid == 0) s_tk = atomicAdd(&g_sync[C_TICKET], 1u);
        __syncthreads();
        const unsigned tk = s_tk;
        __syncthreads();
        if (tk >= T_END) break;

        if (tk < N_V) {                                    // ---- pack V
            pack_v_chunk(tk, v_t, v_d);
            __threadfence();
            __syncthreads();
            if (tid == 0) redrel(&g_sync[C_V]);
        } else if (tk < T_G1) {                            // ---- pack x chunk
            const int q = tk - T_X0;                       // 0..511
            pack_x_chunk(q, x);
            __threadfence();
            __syncthreads();
            if (tid == 0) redrel(&g_sync[C_X + (q >> 3)]);
        } else if (tk < T_US0) {                           // ---- GEMM1 tile 128x128
            const int id = tk - T_G1;
            const int m = id >> 3, n = id & 7;
            if (tid == 0) wait_ge(&g_sync[C_X + m], XPB);
            else if (tid == 32) wait_ge(&g_sync[C_V], N_V);
            __syncthreads();
            gemm_tile<true, BN1>(sm, g_xt, g_V, nullptr, g_t, 1024, 4096, m * BM, n * BN1);
            __threadfence();
            __syncthreads();
            if (tid == 0) redrel(&g_sync[C_T + m]);
        } else if (tk < T_G2A) {                           // ---- pack Us (GEMM2-only dep)
            pack_us_chunk(tk - T_US0, u_t, u_d, s);
            __threadfence();
            __syncthreads();
            if (tid == 0) redrel(&g_sync[C_US]);
        } else if (tk < T_G2B) {                           // ---- GEMM2 tile 128x128 (bands 0..55)
            const int id = tk - T_G2A;
            const int m = id >> 5, n = id & 31;
            if (tid == 0) wait_ge(&g_sync[C_T + m], 8);
            else if (tid == 32) wait_ge(&g_sync[C_US], N_US);
            __syncthreads();
            gemm_tile<false, BN1>(sm, g_t, g_Us, bias, out, 4096, 1024, m * BM, n * BN1);
        } else {                                           // ---- GEMM2 tail 128x64 (bands 56..63)
            const int id = tk - T_G2B;
            const int m = 56 + (id >> 6), n = id & 63;
            if (tid == 0) wait_ge(&g_sync[C_T + m], 8);
            else if (tid == 32) wait_ge(&g_sync[C_US], N_US);
            __syncthreads();
            gemm_tile<false, BN2>(sm, g_t, g_Us, bias, out, 4096, 1024, m * BM, n * BN2);
        }
    }
}

// ---------------- host ----------------
extern "C" void kernel_launch(void* const* d_in, const int* in_sizes, int n_in,
                              void* d_out, int out_size)
{
    const float* x    = (const float*)d_in[0];
    const float* u_t  = (const float*)d_in[1];
    const float* u_d  = (const float*)d_in[2];
    const float* s    = (const float*)d_in[3];
    const float* v_t  = (const float*)d_in[4];
    const float* v_d  = (const float*)d_in[5];
    const float* bias = (const float*)d_in[6];
    float* out = (float*)d_out;
    (void)in_sizes; (void)n_in; (void)out_size;

    void* syncPtr = nullptr;
    cudaGetSymbolAddress(&syncPtr, g_sync);
    cudaMemsetAsync(syncPtr, 0, C_NUM * sizeof(unsigned));

    cudaFuncSetAttribute(siva_fused,
                         cudaFuncAttributeMaxDynamicSharedMemorySize, SMEM_BYTES);

    int dev = 0, smc = 148;
    cudaGetDevice(&dev);
    cudaDeviceGetAttribute(&smc, cudaDevAttrMultiProcessorCount, dev);

    siva_fused<<<smc * 2, 128, SMEM_BYTES>>>(x, u_t, u_d, s, v_t, v_d, bias, out);
}

// round 15
// speedup vs baseline: 1.5366x; 1.5366x over previous
#include <cuda_runtime.h>
#include <cuda_fp16.h>
#include <cstdint>

// ---------------- tiles (measured best: R11/R13 config) ----------------
#define BM 128
#define BN 128
#define BK 64
#define STAGES 3
#define ROWB 144
#define A_STAGE_B (BM * ROWB)                     // 18432
#define STAGE_B   (2 * A_STAGE_B)                 // 36864
#define SMEM_BYTES (STAGES * STAGE_B)             // 110592 (2 CTAs/SM)

// ---------------- ticket layout: V, x, Us, G1, G2 ----------------
#define N_V    32
#define N_US   32
#define XPB    8
#define N_XB   64
#define T_X0   (N_V)                        // 32
#define T_US0  (T_X0 + N_XB * XPB)          // 544
#define T_G1   (T_US0 + N_US)               // 576
#define N_G1   512                           // 64 bands x 8 tiles
#define T_G2   (T_G1 + N_G1)                // 1088
#define N_G2   2048                          // 64 bands x 32 tiles
#define T_END  (T_G2 + N_G2)                // 3136

// ---------------- sync counters ----------------
#define C_TICKET 0
#define C_US     1
#define C_V      2
#define C_X      3           // 3..66
#define C_T      67          // 67..130
#define C_NUM    131

__device__ unsigned g_sync[C_NUM];

// ---------------- scratch (allocation-free rule) ----------------
__device__ __align__(1024) __half g_xt[33554432]; // x  -> fp16   [8192,4096]
__device__ __align__(1024) __half g_t [8388608];  // t = x @ V^T  [8192,1024]
__device__ __align__(1024) __half g_Us[4194304];  // (U cat)*s    [4096,1024]
__device__ __align__(1024) __half g_V [4194304];  // V cat        [1024,4096]

// ---------------- helpers ----------------
__device__ __forceinline__ void cp16(uint32_t s, const void* g) {
    asm volatile("cp.async.cg.shared.global [%0], [%1], 16;" :: "r"(s), "l"(g));
}
__device__ __forceinline__ void ldsm4(uint32_t* r, uint32_t addr) {
    asm volatile("ldmatrix.sync.aligned.m8n8.x4.shared.b16 {%0,%1,%2,%3}, [%4];"
                 : "=r"(r[0]), "=r"(r[1]), "=r"(r[2]), "=r"(r[3]) : "r"(addr));
}
__device__ __forceinline__ void mma16(float* c, const uint32_t* a, const uint32_t* b) {
    asm volatile("mma.sync.aligned.m16n8k16.row.col.f32.f16.f16.f32 "
                 "{%0,%1,%2,%3}, {%4,%5,%6,%7}, {%8,%9}, {%0,%1,%2,%3};"
                 : "+f"(c[0]), "+f"(c[1]), "+f"(c[2]), "+f"(c[3])
                 : "r"(a[0]), "r"(a[1]), "r"(a[2]), "r"(a[3]),
                   "r"(b[0]), "r"(b[1]));
}
__device__ __forceinline__ unsigned ldacq(const unsigned* p) {
    unsigned v;
    asm volatile("ld.acquire.gpu.global.u32 %0, [%1];" : "=r"(v) : "l"(p));
    return v;
}
__device__ __forceinline__ void redrel(unsigned* p) {
    asm volatile("red.release.gpu.global.add.u32 [%0], %1;" :: "l"(p), "r"(1u));
}
__device__ __forceinline__ void wait_ge(const unsigned* p, unsigned tgt) {
    while (ldacq(p) < tgt) __nanosleep(64);
}

// ---------------- pack pieces (128 threads each) ----------------
__device__ void pack_us_chunk(int c, const float* u_t, const float* u_d, const float* s) {
    const int base = c * 32768;
    for (int i = threadIdx.x; i < 32768; i += 128) {
        const int idx = base + i;
        const int o = idx >> 8, r4 = idx & 255;
        float4 u = (r4 < 16) ? *(const float4*)(u_t + o * 64 + r4 * 4)
                             : *(const float4*)(u_d + o * 960 + r4 * 4 - 64);
        float4 sv = *(const float4*)(s + r4 * 4);
        __half2 h0 = __float22half2_rn(make_float2(u.x * sv.x, u.y * sv.y));
        __half2 h1 = __float22half2_rn(make_float2(u.z * sv.z, u.w * sv.w));
        *(uint2*)(g_Us + (size_t)idx * 4) = make_uint2(*(uint32_t*)&h0, *(uint32_t*)&h1);
    }
}
__device__ void pack_v_chunk(int c, const float* v_t, const float* v_d) {
    const int base = c * 32768;
    for (int i = threadIdx.x; i < 32768; i += 128) {
        const int idx = base + i;
        const int r = idx >> 10;
        float4 v = (r < 64) ? *(const float4*)(v_t + (size_t)idx * 4)
                            : *(const float4*)(v_d + (size_t)idx * 4 - 64 * 4096);
        __half2 h0 = __float22half2_rn(make_float2(v.x, v.y));
        __half2 h1 = __float22half2_rn(make_float2(v.z, v.w));
        *(uint2*)(g_V + (size_t)idx * 4) = make_uint2(*(uint32_t*)&h0, *(uint32_t*)&h1);
    }
}
__device__ void pack_x_chunk(int q, const float* x) {   // q in 0..511
    const size_t base = (size_t)q * 16384;
    for (int i = threadIdx.x; i < 16384; i += 128) {
        const size_t idx = base + i;
        float4 v = *(const float4*)(x + idx * 4);
        __half2 h0 = __float22half2_rn(make_float2(v.x, v.y));
        __half2 h1 = __float22half2_rn(make_float2(v.z, v.w));
        *(uint2*)(g_xt + idx * 4) = make_uint2(*(uint32_t*)&h0, *(uint32_t*)&h1);
    }
}

// ---------------- GEMM tile: C[128x128] = A @ B^T (+bias) ----------------
template<bool HALF_OUT>
__device__ void gemm_tile(char* sm, const __half* __restrict__ A, const __half* __restrict__ Bm,
                          const float* __restrict__ bias, void* __restrict__ Cout,
                          int N, int K, int mBase, int nBase)
{
    const uint32_t sbase = (uint32_t)__cvta_generic_to_shared(sm);
    const int tid  = threadIdx.x;
    const int lane = tid & 31;
    const int wid  = tid >> 5;
    const int wm   = wid >> 1;
    const int wn   = wid & 1;
    const int g    = lane >> 2;
    const int tg   = lane & 3;

    const __half* Ag = A  + (size_t)mBase * K;
    const __half* Bg = Bm + (size_t)nBase * K;

    const int aRow = wm * 64 + (lane & 7) + ((lane >> 3) & 1) * 8;
    const int aKb  = (lane >> 4) * 16;
    const uint32_t aOff = (uint32_t)(aRow * ROWB + aKb);
    const int bRow = wn * 64 + (lane & 7) + (lane >> 4) * 8;
    const int bKb  = ((lane >> 3) & 1) * 16;
    const uint32_t bOff = (uint32_t)(bRow * ROWB + bKb) + A_STAGE_B;

    float c[4][8][4];
#pragma unroll
    for (int mt = 0; mt < 4; mt++)
#pragma unroll
        for (int nt = 0; nt < 8; nt++)
#pragma unroll
            for (int i = 0; i < 4; i++) c[mt][nt][i] = 0.f;

    auto load_stage = [&](int st, int kt) {
        const uint32_t base = sbase + (uint32_t)st * STAGE_B;
        const size_t kOff = (size_t)kt * BK;
#pragma unroll
        for (int i = 0; i < 8; i++) {
            const int cid = i * 128 + tid;
            const int row = cid >> 3;
            const uint32_t colB = (uint32_t)(cid & 7) * 16u;
            cp16(base + (uint32_t)(row * ROWB) + colB,
                 (const char*)(Ag + (size_t)row * K + kOff) + colB);
            cp16(base + A_STAGE_B + (uint32_t)(row * ROWB) + colB,
                 (const char*)(Bg + (size_t)row * K + kOff) + colB);
        }
        asm volatile("cp.async.commit_group;" ::: "memory");
    };

#pragma unroll
    for (int s = 0; s < STAGES - 1; s++) load_stage(s, s);

    const int KT = K / BK;
    for (int kt = 0; kt < KT; kt++) {
        asm volatile("cp.async.wait_group %0;" :: "n"(STAGES - 2) : "memory");
        __syncthreads();

        const int pf = kt + STAGES - 1;
        if (pf < KT) load_stage(pf % STAGES, pf);
        else asm volatile("cp.async.commit_group;" ::: "memory");

        const uint32_t stBase = sbase + (uint32_t)(kt % STAGES) * STAGE_B;

#pragma unroll
        for (int kk = 0; kk < BK / 16; kk++) {
            const uint32_t kByte = (uint32_t)(kk * 32);
            uint32_t a[4][4];
#pragma unroll
            for (int mt = 0; mt < 4; mt++)
                ldsm4(a[mt], stBase + aOff + (uint32_t)(mt * 16 * ROWB) + kByte);
#pragma unroll
            for (int np = 0; np < 4; np++) {
                uint32_t b[4];
                ldsm4(b, stBase + bOff + (uint32_t)(np * 16 * ROWB) + kByte);
#pragma unroll
                for (int mt = 0; mt < 4; mt++) {
                    mma16(c[mt][np * 2],     a[mt], b);
                    mma16(c[mt][np * 2 + 1], a[mt], b + 2);
                }
            }
        }
    }
    __syncthreads();   // stages consumed; smem reusable by next ticket

#pragma unroll
    for (int mt = 0; mt < 4; mt++) {
        const int row = mBase + wm * 64 + mt * 16 + g;
#pragma unroll
        for (int nt = 0; nt < 8; nt++) {
            const int col = nBase + wn * 64 + nt * 8 + 2 * tg;
            if (HALF_OUT) {
                __half* C = (__half*)Cout;
                *(__half2*)(C + (size_t)row * N + col) =
                    __float22half2_rn(make_float2(c[mt][nt][0], c[mt][nt][1]));
                *(__half2*)(C + (size_t)(row + 8) * N + col) =
                    __float22half2_rn(make_float2(c[mt][nt][2], c[mt][nt][3]));
            } else {
                float* C = (float*)Cout;
                const float b0 = bias[col], b1 = bias[col + 1];
                *(float2*)(C + (size_t)row * N + col) =
                    make_float2(c[mt][nt][0] + b0, c[mt][nt][1] + b1);
                *(float2*)(C + (size_t)(row + 8) * N + col) =
                    make_float2(c[mt][nt][2] + b0, c[mt][nt][3] + b1);
            }
        }
    }
}

// ---------------- fused persistent kernel ----------------
__global__ void __launch_bounds__(128, 2)
siva_fused(const float* __restrict__ x,
           const float* __restrict__ u_t, const float* __restrict__ u_d,
           const float* __restrict__ s,
           const float* __restrict__ v_t, const float* __restrict__ v_d,
           const float* __restrict__ bias, float* __restrict__ out)
{
    extern __shared__ __align__(16) char sm[];
    __shared__ unsigned s_tk;
    const int tid = threadIdx.x;

    for (;;) {
        if (tid == 0) s_tk = atomicAdd(&g_sync[C_TICKET], 1u);
        __syncthreads();
        const unsigned tk = s_tk;
        __syncthreads();
        if (tk >= T_END) break;

        if (tk < N_V) {                                    // ---- pack V (first)
            pack_v_chunk(tk, v_t, v_d);
            __threadfence();
            __syncthreads();
            if (tid == 0) redrel(&g_sync[C_V]);
        } else if (tk < T_US0) {                           // ---- pack x chunk
            const int q = tk - T_X0;                       // 0..511
            pack_x_chunk(q, x);
            __threadfence();
            __syncthreads();
            if (tid == 0) redrel(&g_sync[C_X + (q >> 3)]);
        } else if (tk < T_G1) {                            // ---- pack Us (GEMM2-only dep)
            pack_us_chunk(tk - T_US0, u_t, u_d, s);
            __threadfence();
            __syncthreads();
            if (tid == 0) redrel(&g_sync[C_US]);
        } else if (tk < T_G2) {                            // ---- GEMM1 tile 128x128
            const int id = tk - T_G1;
            const int m = id >> 3, n = id & 7;
            if (tid == 0) wait_ge(&g_sync[C_X + m], XPB);
            else if (tid == 32) wait_ge(&g_sync[C_V], N_V);
            __syncthreads();
            gemm_tile<true>(sm, g_xt, g_V, nullptr, g_t, 1024, 4096, m * BM, n * BN);
            __threadfence();
            __syncthreads();
            if (tid == 0) redrel(&g_sync[C_T + m]);
        } else {                                           // ---- GEMM2 tile 128x128
            const int id = tk - T_G2;
            const int m = id >> 5, n = id & 31;
            if (tid == 0) wait_ge(&g_sync[C_T + m], 8);
            else if (tid == 32) wait_ge(&g_sync[C_US], N_US);
            __syncthreads();
            gemm_tile<false>(sm, g_t, g_Us, bias, out, 4096, 1024, m * BM, n * BN);
        }
    }
}

// ---------------- host ----------------
extern "C" void kernel_launch(void* const* d_in, const int* in_sizes, int n_in,
                              void* d_out, int out_size)
{
    const float* x    = (const float*)d_in[0];
    const float* u_t  = (const float*)d_in[1];
    const float* u_d  = (const float*)d_in[2];
    const float* s    = (const float*)d_in[3];
    const float* v_t  = (const float*)d_in[4];
    const float* v_d  = (const float*)d_in[5];
    const float* bias = (const float*)d_in[6];
    float* out = (float*)d_out;
    (void)in_sizes; (void)n_in; (void)out_size;

    void* syncPtr = nullptr;
    cudaGetSymbolAddress(&syncPtr, g_sync);
    cudaMemsetAsync(syncPtr, 0, C_NUM * sizeof(unsigned));

    cudaFuncSetAttribute(siva_fused,
                         cudaFuncAttributeMaxDynamicSharedMemorySize, SMEM_BYTES);

    int dev = 0, smc = 148;
    cudaGetDevice(&dev);
    cudaDeviceGetAttribute(&smc, cudaDevAttrMultiProcessorCount, dev);

    siva_fused<<<smc * 2, 128, SMEM_BYTES>>>(x, u_t, u_d, s, v_t, v_d, bias, out);
}